// round 11
// baseline (speedup 1.0000x reference)
#include <cuda_runtime.h>

// Problem constants
#define NBINS   256
#define NB      257          // nbins + 1 histogram bins before dropping bin 0
#define CH      3
#define NIMG    32
#define ELEMS_PER_IMG (512 * 512 * CH)       // 786432 floats
#define VEC_PER_IMG   (ELEMS_PER_IMG / 4)    // 196608 float4
#define KEYS    (CH * NB)                    // 771 (channel,bin) keys

#define BPI      36          // blocks per image -> grid (36, 32) = 1152 CTAs (occ ~92%)
#define THREADS  256
#define STRIDE   (BPI * THREADS)             // 9216 vec4; floats stride ≡ 0 (mod 3)

// Static scratch (BSS-zeroed at load). Invariant: all-zero on entry to every
// kernel_launch call — each CTA re-zeros its g_part slice in its epilogue and
// the last CTA per image re-zeros the image's g_hist slice after finalize.
__device__ unsigned int g_hist[NIMG * KEYS];
__device__ unsigned int g_part[NIMG * BPI * KEYS];   // per-CTA private replicas (3.55 MB)
__device__ unsigned int g_done[NIMG];

// bin = clip(floor(RN_f32(x / BW)), 0, 256) with BW = f32(1/257), matching the
// reference's IEEE f32 division (double-float multiply, one final rounding).
__device__ __forceinline__ int bin_of(float x) {
    const double invd   = 1.0 / (double)(1.0f / 257.0f);   // compile-time constant
    const float  inv_hi = (float)invd;
    const float  inv_lo = (float)(invd - (double)inv_hi);
    float q = fmaf(x, inv_hi, x * inv_lo);
    int k = (int)q;                      // q >= 0 -> trunc == floor
    return min(k, NB - 1);               // x<1 can round up to exactly 257.0
}

__global__ void __launch_bounds__(THREADS)
hist_kernel(const float* __restrict__ in, float* __restrict__ out) {
    __shared__ unsigned int sh[KEYS];    // per-CTA shared histogram, 3084 B
    __shared__ bool is_last;

    const int b   = blockIdx.y;
    const int tid = threadIdx.x;

    for (int i = tid; i < KEYS; i += THREADS) sh[i] = 0u;
    __syncthreads();

    // Channel pattern is loop-invariant: stride in floats = 36864 ≡ 0 (mod 3).
    const int i0 = blockIdx.x * THREADS + tid;
    const int c0 = (4 * i0) % 3;
    int c1 = c0 + 1; if (c1 == 3) c1 = 0;
    int c2 = c1 + 1; if (c2 == 3) c2 = 0;
    const int k0b = c0 * NB, k1b = c1 * NB, k2b = c2 * NB, k3b = c0 * NB;

    // This CTA's private global replica: zero inter-CTA contention on L2 atomics.
    unsigned int* gp = &g_part[((size_t)b * BPI + blockIdx.x) * KEYS];

    const float4* img = (const float4*)(in + (size_t)b * ELEMS_PER_IMG);

    // Backend split: .x,.y -> shared-ATOMS unit; .z,.w -> L2 atomic ALUs (REDG,
    // result unused). Halves the load on each atomic backend.
    #pragma unroll 4
    for (int i = i0; i < VEC_PER_IMG; i += STRIDE) {
        float4 v = img[i];
        atomicAdd(&sh[k0b + bin_of(v.x)], 1u);
        atomicAdd(&sh[k1b + bin_of(v.y)], 1u);
        atomicAdd(&gp[k2b + bin_of(v.z)], 1u);
        atomicAdd(&gp[k3b + bin_of(v.w)], 1u);
    }
    __threadfence();                     // our REDGs to gp visible to our own LDGs
    __syncthreads();

    // Merge shared + private-global parts; one global atomic per key per CTA.
    // Also re-zero this CTA's gp slice for the next graph replay.
    unsigned int* gh = &g_hist[b * KEYS];
    for (int j = tid; j < KEYS; j += THREADS) {
        unsigned int s = sh[j] + __ldcg(&gp[j]);
        if (s) atomicAdd(&gh[j], s);
        gp[j] = 0u;
    }

    // Last-block finalize for this image.
    __threadfence();
    if (tid == 0) {
        unsigned int old = atomicAdd(&g_done[b], 1u);
        is_last = (old == BPI - 1);
    }
    __syncthreads();
    if (!is_last) return;

    // ---- finalize image b (256 threads; t -> histogram bin t+1) ----
    const int t = tid;
    float* fsum = (float*)sh;            // reuse smem for warp sums + denom

    float v[CH];
    #pragma unroll
    for (int c = 0; c < CH; c++)
        v[c] = (float)__ldcg(&gh[c * NB + (t + 1)]);   // L2 read: sees all atomics

    #pragma unroll
    for (int c = 0; c < CH; c++) {
        float s = v[c];
        #pragma unroll
        for (int o = 16; o; o >>= 1) s += __shfl_xor_sync(0xffffffffu, s, o);
        if ((t & 31) == 0) fsum[c * 8 + (t >> 5)] = s;
    }
    __syncthreads();
    if (t < CH) {
        float s = 0.f;
        #pragma unroll
        for (int w = 0; w < 8; w++) s += fsum[t * 8 + w];
        fsum[24 + t] = fmaxf(s, 1e-7f);  // denom[c]
    }
    __syncthreads();

    #pragma unroll
    for (int c = 0; c < CH; c++)
        out[((size_t)b * NBINS + t) * CH + c] = v[c] / fsum[24 + c];

    // Re-zero this image's g_hist slice for the next graph replay.
    for (int j = t; j < KEYS; j += THREADS) gh[j] = 0u;
    if (t == 0) g_done[b] = 0u;
}

extern "C" void kernel_launch(void* const* d_in, const int* in_sizes, int n_in,
                              void* d_out, int out_size) {
    const float* in = (const float*)d_in[0];
    float* out = (float*)d_out;

    dim3 grid(BPI, NIMG);
    hist_kernel<<<grid, THREADS>>>(in, out);
}

// round 12
// speedup vs baseline: 5.6091x; 5.6091x over previous
#include <cuda_runtime.h>

// Problem constants
#define NBINS   256
#define NB      257          // nbins + 1 histogram bins before dropping bin 0
#define CH      3
#define NIMG    32
#define ELEMS_PER_IMG (512 * 512 * CH)       // 786432 floats
#define VEC_PER_IMG   (ELEMS_PER_IMG / 4)    // 196608 float4
#define KEYS    (CH * NB)                    // 771 (channel,bin) keys

#define BPI      18          // blocks per image -> grid (18, 32) = 576 CTAs
#define THREADS  512         // 16 warps/CTA; 4 CTAs/SM = 64 warps (full occupancy)
#define STRIDE   (BPI * THREADS)             // 9216 vec4; float stride 36864 ≡ 0 mod 3

// Static scratch (BSS-zeroed at load). Invariant: all-zero on entry to every
// kernel_launch call — the last CTA per image re-zeros its slice after finalize.
__device__ unsigned int g_hist[NIMG * KEYS];
__device__ unsigned int g_done[NIMG];

// bin = clip(floor(RN_f32(x / BW)), 0, 256) with BW = f32(1/257), matching the
// reference's IEEE f32 division (double-float multiply, one final rounding).
__device__ __forceinline__ int bin_of(float x) {
    const double invd   = 1.0 / (double)(1.0f / 257.0f);   // compile-time constant
    const float  inv_hi = (float)invd;
    const float  inv_lo = (float)(invd - (double)inv_hi);
    float q = fmaf(x, inv_hi, x * inv_lo);
    int k = (int)q;                      // q >= 0 -> trunc == floor
    return min(k, NB - 1);               // x<1 can round up to exactly 257.0
}

__global__ void __launch_bounds__(THREADS)
hist_kernel(const float* __restrict__ in, float* __restrict__ out) {
    __shared__ unsigned int sh[KEYS];    // per-CTA histogram, 3084 B
    __shared__ bool is_last;

    const int b   = blockIdx.y;
    const int tid = threadIdx.x;

    for (int i = tid; i < KEYS; i += THREADS) sh[i] = 0u;
    __syncthreads();

    // Channel pattern is loop-invariant: stride in floats = 36864 ≡ 0 (mod 3).
    const int i0 = blockIdx.x * THREADS + tid;
    const int c0 = (4 * i0) % 3;
    int c1 = c0 + 1; if (c1 == 3) c1 = 0;
    int c2 = c1 + 1; if (c2 == 3) c2 = 0;
    const int k0b = c0 * NB, k1b = c1 * NB, k2b = c2 * NB, k3b = c0 * NB;

    const float4* img = (const float4*)(in + (size_t)b * ELEMS_PER_IMG);

    // 21 full iterations + tail (threads with i0 < 3072) — identical loop shape
    // to the proven 22.8us kernel; only the CTA shape changed.
    #pragma unroll 4
    for (int i = i0; i < VEC_PER_IMG; i += STRIDE) {
        float4 v = img[i];
        atomicAdd(&sh[k0b + bin_of(v.x)], 1u);
        atomicAdd(&sh[k1b + bin_of(v.y)], 1u);
        atomicAdd(&sh[k2b + bin_of(v.z)], 1u);
        atomicAdd(&sh[k3b + bin_of(v.w)], 1u);
    }
    __syncthreads();

    // One global atomic per key per CTA (771 * 576 total).
    unsigned int* gh = &g_hist[b * KEYS];
    for (int j = tid; j < KEYS; j += THREADS) {
        unsigned int s = sh[j];
        if (s) atomicAdd(&gh[j], s);
    }

    // Last-block finalize for this image.
    __threadfence();
    if (tid == 0) {
        unsigned int old = atomicAdd(&g_done[b], 1u);
        is_last = (old == BPI - 1);
    }
    __syncthreads();
    if (!is_last) return;

    // ---- finalize image b (first 256 threads; t -> histogram bin t+1) ----
    const int t = tid;
    float* fsum = (float*)sh;            // reuse smem for warp sums + denom

    float v[CH];
    if (t < NBINS) {
        #pragma unroll
        for (int c = 0; c < CH; c++)
            v[c] = (float)__ldcg(&gh[c * NB + (t + 1)]);   // L2 read: sees all atomics

        #pragma unroll
        for (int c = 0; c < CH; c++) {
            float s = v[c];
            #pragma unroll
            for (int o = 16; o; o >>= 1) s += __shfl_xor_sync(0xffffffffu, s, o);
            if ((t & 31) == 0) fsum[c * 8 + (t >> 5)] = s;
        }
    }
    __syncthreads();
    if (t < CH) {
        float s = 0.f;
        #pragma unroll
        for (int w = 0; w < 8; w++) s += fsum[t * 8 + w];
        fsum[24 + t] = fmaxf(s, 1e-7f);  // denom[c]
    }
    __syncthreads();

    if (t < NBINS) {
        #pragma unroll
        for (int c = 0; c < CH; c++)
            out[((size_t)b * NBINS + t) * CH + c] = v[c] / fsum[24 + c];
    }

    // Re-zero this image's scratch for the next graph replay (all 512 threads).
    for (int j = t; j < KEYS; j += THREADS) gh[j] = 0u;
    if (t == 0) g_done[b] = 0u;
}

extern "C" void kernel_launch(void* const* d_in, const int* in_sizes, int n_in,
                              void* d_out, int out_size) {
    const float* in = (const float*)d_in[0];
    float* out = (float*)d_out;

    dim3 grid(BPI, NIMG);
    hist_kernel<<<grid, THREADS>>>(in, out);
}

// round 13
// speedup vs baseline: 5.6170x; 1.0014x over previous
#include <cuda_runtime.h>

// Problem constants
#define NBINS   256
#define NB      257          // nbins + 1 histogram bins before dropping bin 0
#define CH      3
#define NIMG    32
#define ELEMS_PER_IMG (512 * 512 * CH)       // 786432 floats
#define VEC_PER_IMG   (ELEMS_PER_IMG / 4)    // 196608 float4
#define KEYS    (CH * NB)                    // 771 (channel,bin) keys

#define BPI      18          // blocks per image -> grid (18, 32) = 576 CTAs
#define THREADS  512         // 4 CTAs/SM = 64 warps -> full single-wave occupancy
#define STRIDE   (BPI * THREADS)             // 9216 vec4; float stride 36864 ≡ 0 mod 3
#define FULL_ITERS 21                        // guaranteed for every thread
#define TAIL_CUT   (VEC_PER_IMG - FULL_ITERS * STRIDE)   // 3072: i0 < 3072 -> 22nd iter

// Static scratch (BSS-zeroed at load). Invariant: all-zero on entry to every
// kernel_launch call — the last CTA per image re-zeros its slice after finalize.
__device__ unsigned int g_hist[NIMG * KEYS];
__device__ unsigned int g_done[NIMG];

// bin = clip(floor(RN_f32(x / BW)), 0, 256) with BW = f32(1/257), matching the
// reference's IEEE f32 division (double-float multiply, one final rounding).
__device__ __forceinline__ int bin_of(float x) {
    const double invd   = 1.0 / (double)(1.0f / 257.0f);   // compile-time constant
    const float  inv_hi = (float)invd;
    const float  inv_lo = (float)(invd - (double)inv_hi);
    float q = fmaf(x, inv_hi, x * inv_lo);
    int k = (int)q;                      // q >= 0 -> trunc == floor
    return min(k, NB - 1);               // x<1 can round up to exactly 257.0
}

__global__ void __launch_bounds__(THREADS)
hist_kernel(const float* __restrict__ in, float* __restrict__ out) {
    __shared__ unsigned int sh[KEYS];    // per-CTA histogram, 3084 B
    __shared__ bool is_last;

    const int b   = blockIdx.y;
    const int tid = threadIdx.x;

    for (int i = tid; i < KEYS; i += THREADS) sh[i] = 0u;
    __syncthreads();

    // Channel pattern is loop-invariant: stride in floats = 36864 ≡ 0 (mod 3).
    const int i0 = blockIdx.x * THREADS + tid;
    const int c0 = (4 * i0) % 3;
    int c1 = c0 + 1; if (c1 == 3) c1 = 0;
    int c2 = c1 + 1; if (c2 == 3) c2 = 0;
    const int k0b = c0 * NB, k1b = c1 * NB, k2b = c2 * NB, k3b = c0 * NB;

    const float4* img = (const float4*)(in + (size_t)b * ELEMS_PER_IMG);

    // 21 guaranteed iterations (branch-free counted loop, unroll 7 -> 3 back
    // edges), then one predicated tail body for threads with i0 < 3072.
    int i = i0;
    #pragma unroll 7
    for (int m = 0; m < FULL_ITERS; m++, i += STRIDE) {
        float4 v = img[i];
        atomicAdd(&sh[k0b + bin_of(v.x)], 1u);
        atomicAdd(&sh[k1b + bin_of(v.y)], 1u);
        atomicAdd(&sh[k2b + bin_of(v.z)], 1u);
        atomicAdd(&sh[k3b + bin_of(v.w)], 1u);
    }
    if (i0 < TAIL_CUT) {
        float4 v = img[i];
        atomicAdd(&sh[k0b + bin_of(v.x)], 1u);
        atomicAdd(&sh[k1b + bin_of(v.y)], 1u);
        atomicAdd(&sh[k2b + bin_of(v.z)], 1u);
        atomicAdd(&sh[k3b + bin_of(v.w)], 1u);
    }
    __syncthreads();

    // One global atomic per key per CTA (771 * 576 total).
    unsigned int* gh = &g_hist[b * KEYS];
    for (int j = tid; j < KEYS; j += THREADS) {
        unsigned int s = sh[j];
        if (s) atomicAdd(&gh[j], s);
    }

    // Last-block finalize for this image.
    __threadfence();
    if (tid == 0) {
        unsigned int old = atomicAdd(&g_done[b], 1u);
        is_last = (old == BPI - 1);
    }
    __syncthreads();
    if (!is_last) return;

    // ---- finalize image b (first 256 threads; t -> histogram bin t+1) ----
    const int t = tid;
    float* fsum = (float*)sh;            // reuse smem for warp sums + denom

    float v[CH];
    if (t < NBINS) {
        #pragma unroll
        for (int c = 0; c < CH; c++)
            v[c] = (float)__ldcg(&gh[c * NB + (t + 1)]);   // L2 read: sees all atomics

        #pragma unroll
        for (int c = 0; c < CH; c++) {
            float s = v[c];
            #pragma unroll
            for (int o = 16; o; o >>= 1) s += __shfl_xor_sync(0xffffffffu, s, o);
            if ((t & 31) == 0) fsum[c * 8 + (t >> 5)] = s;
        }
    }
    __syncthreads();
    if (t < CH) {
        float s = 0.f;
        #pragma unroll
        for (int w = 0; w < 8; w++) s += fsum[t * 8 + w];
        fsum[24 + t] = fmaxf(s, 1e-7f);  // denom[c]
    }
    __syncthreads();

    if (t < NBINS) {
        #pragma unroll
        for (int c = 0; c < CH; c++)
            out[((size_t)b * NBINS + t) * CH + c] = v[c] / fsum[24 + c];
    }

    // Re-zero this image's scratch for the next graph replay (all 512 threads).
    for (int j = t; j < KEYS; j += THREADS) gh[j] = 0u;
    if (t == 0) g_done[b] = 0u;
}

extern "C" void kernel_launch(void* const* d_in, const int* in_sizes, int n_in,
                              void* d_out, int out_size) {
    const float* in = (const float*)d_in[0];
    float* out = (float*)d_out;

    dim3 grid(BPI, NIMG);
    hist_kernel<<<grid, THREADS>>>(in, out);
}